// round 11
// baseline (speedup 1.0000x reference)
#include <cuda_runtime.h>
#include <math.h>

// Problem constants (fixed shapes from reference)
#define BS     4
#define AN     3
#define GR     64
#define CN     13
#define FD     18
#define TN     256
#define NTAR   (BS*TN)          // 1024
#define NCAND  (7*AN*NTAR)      // 21504
#define NCELL  (BS*AN*GR*GR*GR) // 3145728

#define CPT        16
#define OBJ_BLOCKS (NCELL / (256 * CPT))   // 768 -> single resident wave
#define CAND_BLOCKS (NCAND / 256)          // 84
#define CF_BLOCKS  (CAND_BLOCKS + 1)       // 85 (extra block helps finalize)

// Device state. All zero at module load; the finalize path restores
// everything to zero every launch, so graph replays are deterministic.
// Accumulators: 0=sum_w, 1=sum_bbox, 2=sum_cls, 3=sum_p4_set, 4=sum_softplus
__device__ double   g_acc[5];
__device__ int      g_flags[NCELL];   // tobj dedup flags
__device__ int      g_list[NCAND];    // cells claimed this launch (for cheap reset)
__device__ int      g_nlist;
__device__ unsigned g_done;

__constant__ float c_off[7][3] = {
    {0.f,0.f,0.f},{0.5f,0.f,0.f},{0.f,0.5f,0.f},{0.f,0.f,0.5f},
    {-0.5f,0.f,0.f},{0.f,-0.5f,0.f},{0.f,0.f,-0.5f}
};

__device__ __forceinline__ float softplusf(float x) {
    return fmaxf(x, 0.f) + log1pf(__expf(-fabsf(x)));
}
__device__ __forceinline__ float sigmoidf(float x) {
    return 1.f / (1.f + __expf(-x));
}

// Block-sum reduce; result valid on thread 0.
__device__ __forceinline__ float block_reduce(float v, float* sh) {
    __syncthreads();  // allow shared reuse across consecutive calls
    #pragma unroll
    for (int o = 16; o; o >>= 1) v += __shfl_down_sync(0xffffffffu, v, o);
    int lane = threadIdx.x & 31, w = threadIdx.x >> 5;
    if (lane == 0) sh[w] = v;
    __syncthreads();
    if (w == 0) {
        v = (lane < (int)(blockDim.x >> 5)) ? sh[lane] : 0.f;
        #pragma unroll
        for (int o = 16; o; o >>= 1) v += __shfl_down_sync(0xffffffffu, v, o);
    }
    return v;
}

// Candidate geometry: validity + cell index + box geometry.
__device__ __forceinline__ bool cand_geom(
    int tid, const float* __restrict__ targets, const float* __restrict__ anchor,
    int& cell, float& tbx, float& tby, float& tbz, float& rn, float& an,
    const float*& xrow)
{
    int t = tid & (NTAR - 1);
    int a = (tid >> 10) % AN;
    int o = tid / (AN * NTAR);
    const float* x = targets + t * FD;
    xrow = x;
    int b = t / TN;

    if (!(x[4] > 0.5f)) return false;                 // conf_m
    rn = x[3] * 0.25f;
    an = anchor[a] * 0.25f;
    float ratio = rn / an;
    if (!(fmaxf(ratio, 1.f / ratio) < 4.f)) return false;  // aok

    float gx = x[0] * 0.25f, gy = x[1] * 0.25f, gz = x[2] * 0.25f;

    bool fmv = true;
    if (o >= 1 && o <= 3) {
        float v = (o == 1) ? gx : (o == 2) ? gy : gz;
        fmv = ((v - floorf(v)) < 0.5f) && (v > 1.f);
    } else if (o >= 4) {
        float v0 = (o == 4) ? gx : (o == 5) ? gy : gz;
        float v = 64.f - v0;
        fmv = ((v - floorf(v)) < 0.5f) && (v > 1.f);
    }
    if (!fmv) return false;

    float fx = truncf(gx - c_off[o][0]);
    float fy = truncf(gy - c_off[o][1]);
    float fz = truncf(gz - c_off[o][2]);
    int gi = min(max(__float2int_rz(fx), 0), GR - 1);
    int gj = min(max(__float2int_rz(fy), 0), GR - 1);
    int gk = min(max(__float2int_rz(fz), 0), GR - 1);
    cell = (((b * AN + a) * GR + gk) * GR + gj) * GR + gi;
    tbx = gx - fx; tby = gy - fy; tbz = gz - fz;
    return true;
}

// Lean streaming kernel: ONLY the softplus(p4) reduction. No candidate code
// -> low register count -> 7-8 CTAs/SM resident -> ~2x outstanding loads vs
// the fused kernel (which compiled to 60 regs / 4 CTAs/SM and left DRAM at
// 61% busy). 16 consecutive cells per thread, grid sized to one wave.
__global__ void __launch_bounds__(256) obj_kernel(const float* __restrict__ p)
{
    __shared__ float sh[32];
    int i0 = (blockIdx.x * 256 + threadIdx.x) * CPT;
    float v[CPT];
    #pragma unroll
    for (int k = 0; k < CPT; k++)
        v[k] = __ldg(p + (size_t)(i0 + k) * FD + 4);
    float s = 0.f;
    #pragma unroll
    for (int k = 0; k < CPT; k++)
        s += softplusf(v[k]);
    float r = block_reduce(s, sh);
    if (threadIdx.x == 0) atomicAdd(&g_acc[4], (double)r);
}

// Candidate work + last-block finalize + device-state reset.
__global__ void __launch_bounds__(256) cand_fin_kernel(
    const float* __restrict__ p,
    const float* __restrict__ targets,
    const float* __restrict__ anchor,
    float* __restrict__ out, int out_size)
{
    __shared__ float sh[32];
    __shared__ int s_last;
    int bid = blockIdx.x;

    float lw = 0.f, lbb = 0.f, lcls = 0.f, lp4 = 0.f;
    if (bid < CAND_BLOCKS) {
        int tid = bid * 256 + threadIdx.x;
        int cell; float tbx, tby, tbz, rn, an; const float* x;
        if (cand_geom(tid, targets, anchor, cell, tbx, tby, tbz, rn, an, x)) {
            const float* pr = p + (size_t)cell * FD;
            float pred[FD];
            #pragma unroll
            for (int i = 0; i < FD; i++) pred[i] = __ldg(pr + i);

            // pbox
            float c1x = sigmoidf(pred[0]) * 2.f - 0.5f;
            float c1y = sigmoidf(pred[1]) * 2.f - 0.5f;
            float c1z = sigmoidf(pred[2]) * 2.f - 0.5f;
            float s4  = sigmoidf(pred[3]) * 2.f;
            float r1  = s4 * s4 * an;

            // EIoU(pbox, tbox)
            const float eps = 1e-7f;
            float r2 = rn;
            float h1 = r1 * 0.5f, h2 = r2 * 0.5f;
            float lox = fmaxf(c1x - h1, tbx - h2), hix = fminf(c1x + h1, tbx + h2);
            float loy = fmaxf(c1y - h1, tby - h2), hiy = fminf(c1y + h1, tby + h2);
            float loz = fmaxf(c1z - h1, tbz - h2), hiz = fminf(c1z + h1, tbz + h2);
            float inter = fmaxf(hix - lox, 0.f) * fmaxf(hiy - loy, 0.f) * fmaxf(hiz - loz, 0.f);
            float uni = r1 * r1 * r1 + r2 * r2 * r2 - inter + eps;
            float iou = inter / uni;
            float cdx = fmaxf(c1x + h1, tbx + h2) - fminf(c1x - h1, tbx - h2);
            float cdy = fmaxf(c1y + h1, tby + h2) - fminf(c1y - h1, tby - h2);
            float cdz = fmaxf(c1z + h1, tbz + h2) - fminf(c1z - h1, tbz - h2);
            float dx = c1x - tbx, dy = c1y - tby, dz = c1z - tbz;
            float rho2 = dx * dx + dy * dy + dz * dz;
            float c2diag = cdx * cdx + cdy * cdy + cdz * cdz + eps;
            float dr = r1 - r2; float dr2 = dr * dr;
            float size_pen = dr2 / (cdx * cdx + eps) + dr2 / (cdy * cdy + eps) + dr2 / (cdz * cdz + eps);
            float ei = iou - rho2 / c2diag - size_pen;

            lw  = 1.f;
            lbb = 1.f - ei;

            // class BCE (tcls one-hot 0/1)
            float cs = 0.f;
            #pragma unroll
            for (int c = 0; c < CN; c++) {
                float l = pred[5 + c];
                float tc = x[5 + c];
                cs += tc * softplusf(-l) + (1.f - tc) * softplusf(l);
            }
            lcls = cs;

            // tobj dedup: winner value depends only on the cell -> deterministic.
            if (atomicExch(&g_flags[cell], 1) == 0) {
                lp4 = pred[4];
                g_list[atomicAdd(&g_nlist, 1)] = cell;
            }
        }
    }

    float v;
    v = block_reduce(lw,   sh); if (threadIdx.x == 0 && v != 0.f) atomicAdd(&g_acc[0], (double)v);
    v = block_reduce(lbb,  sh); if (threadIdx.x == 0 && v != 0.f) atomicAdd(&g_acc[1], (double)v);
    v = block_reduce(lcls, sh); if (threadIdx.x == 0 && v != 0.f) atomicAdd(&g_acc[2], (double)v);
    v = block_reduce(lp4,  sh); if (threadIdx.x == 0 && v != 0.f) atomicAdd(&g_acc[3], (double)v);

    // Last finishing block of THIS kernel finalizes. obj_kernel completed
    // earlier in stream order, so g_acc[4] is final.
    if (threadIdx.x == 0) {
        __threadfence();
        unsigned t = atomicAdd(&g_done, 1u);
        s_last = (t == (unsigned)(gridDim.x - 1));
    }
    __syncthreads();
    if (s_last) {
        int n = *(volatile int*)&g_nlist;
        for (int i = threadIdx.x; i < n; i += 256)
            g_flags[g_list[i]] = 0;
        if (threadIdx.x == 0) {
            volatile double* acc = g_acc;
            double sw   = acc[0];
            double sbb  = acc[1];
            double scls = acc[2];
            double sp4  = acc[3];
            double ssp  = acc[4];
            double nv = fmax(sw, 1.0);
            double lb = sbb / nv;                       // loss_bbox * 1.0
            double lc = 10.0 * scls / (nv * (double)CN);
            double lo = 20.0 * (ssp - sp4) / (double)NCELL;
            if (out_size > 0) out[0] = (float)((lb + lo + lc) * (double)BS);
            if (out_size > 1) out[1] = (float)lo;
            if (out_size > 2) out[2] = (float)lc;
            #pragma unroll
            for (int i = 0; i < 5; i++) g_acc[i] = 0.0;
            g_nlist = 0;
            g_done  = 0u;
        }
    }
}

extern "C" void kernel_launch(void* const* d_in, const int* in_sizes, int n_in,
                              void* d_out, int out_size)
{
    const float* p      = (const float*)d_in[0];
    const float* tg     = (const float*)d_in[1];
    const float* anchor = (const float*)d_in[2];
    float* out = (float*)d_out;

    obj_kernel<<<OBJ_BLOCKS, 256>>>(p);
    cand_fin_kernel<<<CF_BLOCKS, 256>>>(p, tg, anchor, out, out_size);
}

// round 13
// speedup vs baseline: 1.2069x; 1.2069x over previous
#include <cuda_runtime.h>
#include <math.h>

// Problem constants (fixed shapes from reference)
#define BS     4
#define AN     3
#define GR     64
#define CN     13
#define FD     18
#define TN     256
#define NTAR   (BS*TN)          // 1024
#define NCAND  (7*AN*NTAR)      // 21504
#define NCELL  (BS*AN*GR*GR*GR) // 3145728

#define CELLS_PER_THREAD 8
#define MAIN_BLOCKS (NCELL / (256 * CELLS_PER_THREAD))  // 1536
#define CAND_BLOCKS (NCAND / 256)                        // 84

// Device state. All zero at module load; fin_kernel restores everything to
// zero every launch, so graph replays are deterministic.
// Accumulators: 0=sum_w, 1=sum_bbox, 2=sum_cls, 3=sum_p4_set, 4=sum_softplus
__device__ double   g_acc[5];
__device__ int      g_flags[NCELL];   // tobj dedup flags
__device__ int      g_list[NCAND];    // cells claimed this launch (for cheap reset)
__device__ int      g_nlist;

__constant__ float c_off[7][3] = {
    {0.f,0.f,0.f},{0.5f,0.f,0.f},{0.f,0.5f,0.f},{0.f,0.f,0.5f},
    {-0.5f,0.f,0.f},{0.f,-0.5f,0.f},{0.f,0.f,-0.5f}
};

__device__ __forceinline__ float softplusf(float x) {
    return fmaxf(x, 0.f) + log1pf(__expf(-fabsf(x)));
}
__device__ __forceinline__ float sigmoidf(float x) {
    return 1.f / (1.f + __expf(-x));
}

// Block-sum reduce; result valid on thread 0.
__device__ __forceinline__ float block_reduce(float v, float* sh) {
    __syncthreads();  // allow shared reuse across consecutive calls
    #pragma unroll
    for (int o = 16; o; o >>= 1) v += __shfl_down_sync(0xffffffffu, v, o);
    int lane = threadIdx.x & 31, w = threadIdx.x >> 5;
    if (lane == 0) sh[w] = v;
    __syncthreads();
    if (w == 0) {
        v = (lane < (int)(blockDim.x >> 5)) ? sh[lane] : 0.f;
        #pragma unroll
        for (int o = 16; o; o >>= 1) v += __shfl_down_sync(0xffffffffu, v, o);
    }
    return v;
}

// Candidate geometry: validity + cell index + box geometry.
__device__ __forceinline__ bool cand_geom(
    int tid, const float* __restrict__ targets, const float* __restrict__ anchor,
    int& cell, float& tbx, float& tby, float& tbz, float& rn, float& an,
    const float*& xrow)
{
    int t = tid & (NTAR - 1);
    int a = (tid >> 10) % AN;
    int o = tid / (AN * NTAR);
    const float* x = targets + t * FD;
    xrow = x;
    int b = t / TN;

    if (!(x[4] > 0.5f)) return false;                 // conf_m
    rn = x[3] * 0.25f;
    an = anchor[a] * 0.25f;
    float ratio = rn / an;
    if (!(fmaxf(ratio, 1.f / ratio) < 4.f)) return false;  // aok

    float gx = x[0] * 0.25f, gy = x[1] * 0.25f, gz = x[2] * 0.25f;

    bool fmv = true;
    if (o >= 1 && o <= 3) {
        float v = (o == 1) ? gx : (o == 2) ? gy : gz;
        fmv = ((v - floorf(v)) < 0.5f) && (v > 1.f);
    } else if (o >= 4) {
        float v0 = (o == 4) ? gx : (o == 5) ? gy : gz;
        float v = 64.f - v0;
        fmv = ((v - floorf(v)) < 0.5f) && (v > 1.f);
    }
    if (!fmv) return false;

    float fx = truncf(gx - c_off[o][0]);
    float fy = truncf(gy - c_off[o][1]);
    float fz = truncf(gz - c_off[o][2]);
    int gi = min(max(__float2int_rz(fx), 0), GR - 1);
    int gj = min(max(__float2int_rz(fy), 0), GR - 1);
    int gk = min(max(__float2int_rz(fz), 0), GR - 1);
    cell = (((b * AN + a) * GR + gk) * GR + gj) * GR + gi;
    tbx = gx - fx; tby = gy - fy; tbz = gz - fz;
    return true;
}

// Fused main kernel (R5 structure: best-known). The ch-4 gather uses __ldcg
// (L2-only, sector-granular) instead of __ldg (nc/tex path) to test whether
// the observed full-tensor DRAM traffic was an L1 line-fill artifact.
__global__ void __launch_bounds__(256) main_kernel(
    const float* __restrict__ p,
    const float* __restrict__ targets,
    const float* __restrict__ anchor)
{
    __shared__ float sh[32];
    int bid = blockIdx.x;

    // ---- obj part: 8 consecutive cells per thread, L2-only loads ----
    int i0 = (bid * 256 + threadIdx.x) * CELLS_PER_THREAD;
    float vobj[CELLS_PER_THREAD];
    #pragma unroll
    for (int k = 0; k < CELLS_PER_THREAD; k++)
        vobj[k] = __ldcg(p + (size_t)(i0 + k) * FD + 4);
    float s = 0.f;
    #pragma unroll
    for (int k = 0; k < CELLS_PER_THREAD; k++)
        s += softplusf(vobj[k]);

    // ---- candidate part (first CAND_BLOCKS blocks only) ----
    float lw = 0.f, lbb = 0.f, lcls = 0.f, lp4 = 0.f;
    bool is_cand_block = (bid < CAND_BLOCKS);
    if (is_cand_block) {
        int tid = bid * 256 + threadIdx.x;
        int cell; float tbx, tby, tbz, rn, an; const float* x;
        if (cand_geom(tid, targets, anchor, cell, tbx, tby, tbz, rn, an, x)) {
            const float* pr = p + (size_t)cell * FD;
            float pred[FD];
            #pragma unroll
            for (int i = 0; i < FD; i++) pred[i] = __ldg(pr + i);

            // pbox
            float c1x = sigmoidf(pred[0]) * 2.f - 0.5f;
            float c1y = sigmoidf(pred[1]) * 2.f - 0.5f;
            float c1z = sigmoidf(pred[2]) * 2.f - 0.5f;
            float s4  = sigmoidf(pred[3]) * 2.f;
            float r1  = s4 * s4 * an;

            // EIoU(pbox, tbox)
            const float eps = 1e-7f;
            float r2 = rn;
            float h1 = r1 * 0.5f, h2 = r2 * 0.5f;
            float lox = fmaxf(c1x - h1, tbx - h2), hix = fminf(c1x + h1, tbx + h2);
            float loy = fmaxf(c1y - h1, tby - h2), hiy = fminf(c1y + h1, tby + h2);
            float loz = fmaxf(c1z - h1, tbz - h2), hiz = fminf(c1z + h1, tbz + h2);
            float inter = fmaxf(hix - lox, 0.f) * fmaxf(hiy - loy, 0.f) * fmaxf(hiz - loz, 0.f);
            float uni = r1 * r1 * r1 + r2 * r2 * r2 - inter + eps;
            float iou = inter / uni;
            float cdx = fmaxf(c1x + h1, tbx + h2) - fminf(c1x - h1, tbx - h2);
            float cdy = fmaxf(c1y + h1, tby + h2) - fminf(c1y - h1, tby - h2);
            float cdz = fmaxf(c1z + h1, tbz + h2) - fminf(c1z - h1, tbz - h2);
            float dx = c1x - tbx, dy = c1y - tby, dz = c1z - tbz;
            float rho2 = dx * dx + dy * dy + dz * dz;
            float c2diag = cdx * cdx + cdy * cdy + cdz * cdz + eps;
            float dr = r1 - r2; float dr2 = dr * dr;
            float size_pen = dr2 / (cdx * cdx + eps) + dr2 / (cdy * cdy + eps) + dr2 / (cdz * cdz + eps);
            float ei = iou - rho2 / c2diag - size_pen;

            lw  = 1.f;
            lbb = 1.f - ei;

            // class BCE (tcls one-hot 0/1)
            float cs = 0.f;
            #pragma unroll
            for (int c = 0; c < CN; c++) {
                float l = pred[5 + c];
                float tc = x[5 + c];
                cs += tc * softplusf(-l) + (1.f - tc) * softplusf(l);
            }
            lcls = cs;

            // tobj dedup: winner value depends only on the cell -> deterministic.
            // Record the claimed cell so fin_kernel can cheaply reset flags.
            if (atomicExch(&g_flags[cell], 1) == 0) {
                lp4 = pred[4];
                g_list[atomicAdd(&g_nlist, 1)] = cell;
            }
        }
    }

    // ---- reductions ----
    float v;
    v = block_reduce(s, sh);
    if (threadIdx.x == 0) atomicAdd(&g_acc[4], (double)v);
    if (is_cand_block) {
        v = block_reduce(lw,   sh); if (threadIdx.x == 0 && v != 0.f) atomicAdd(&g_acc[0], (double)v);
        v = block_reduce(lbb,  sh); if (threadIdx.x == 0 && v != 0.f) atomicAdd(&g_acc[1], (double)v);
        v = block_reduce(lcls, sh); if (threadIdx.x == 0 && v != 0.f) atomicAdd(&g_acc[2], (double)v);
        v = block_reduce(lp4,  sh); if (threadIdx.x == 0 && v != 0.f) atomicAdd(&g_acc[3], (double)v);
    }
}

// Tiny finalize: ONE block. Clears only the claimed flags (list-based, no
// geometry recompute), writes outputs, resets accumulators.
__global__ void fin_kernel(float* out, int out_size)
{
    int n = g_nlist;
    for (int i = threadIdx.x; i < n; i += 256)
        g_flags[g_list[i]] = 0;
    if (threadIdx.x == 0) {
        double sw   = g_acc[0];
        double sbb  = g_acc[1];
        double scls = g_acc[2];
        double sp4  = g_acc[3];
        double ssp  = g_acc[4];
        double nv = fmax(sw, 1.0);
        double lb = sbb / nv;                       // loss_bbox * 1.0
        double lc = 10.0 * scls / (nv * (double)CN);
        double lo = 20.0 * (ssp - sp4) / (double)NCELL;
        if (out_size > 0) out[0] = (float)((lb + lo + lc) * (double)BS);
        if (out_size > 1) out[1] = (float)lo;
        if (out_size > 2) out[2] = (float)lc;
        #pragma unroll
        for (int i = 0; i < 5; i++) g_acc[i] = 0.0;
        g_nlist = 0;
    }
}

extern "C" void kernel_launch(void* const* d_in, const int* in_sizes, int n_in,
                              void* d_out, int out_size)
{
    const float* p      = (const float*)d_in[0];
    const float* tg     = (const float*)d_in[1];
    const float* anchor = (const float*)d_in[2];
    float* out = (float*)d_out;

    main_kernel<<<MAIN_BLOCKS, 256>>>(p, tg, anchor);
    fin_kernel<<<1, 256>>>(out, out_size);
}

// round 14
// speedup vs baseline: 1.3870x; 1.1492x over previous
#include <cuda_runtime.h>
#include <math.h>

// Problem constants (fixed shapes from reference)
#define BS     4
#define AN     3
#define GR     64
#define CN     13
#define FD     18
#define TN     256
#define NTAR   (BS*TN)          // 1024
#define NCAND  (7*AN*NTAR)      // 21504
#define NCELL  (BS*AN*GR*GR*GR) // 3145728

#define CELLS_PER_THREAD 8
#define MAIN_BLOCKS (NCELL / (256 * CELLS_PER_THREAD))  // 1536
#define CAND_BLOCKS (NCAND / 256)                        // 84

// Device state.
// Accumulators: 0=sum_w, 1=sum_bbox, 2=sum_cls, 3=sum_p4_set, 4=sum_softplus
// (zero at load; fin_kernel re-zeroes each launch).
// Dedup uses a GENERATION scheme: launch k claims cells by writing gen=k+1
// into g_flags via atomicExch; first claimant sees old != k+1. g_gen is
// incremented once per launch by fin_kernel, so no flag clearing is ever
// needed and every launch performs identical work -> identical output.
__device__ double   g_acc[5];
__device__ unsigned g_flags[NCELL];
__device__ unsigned g_gen;

__constant__ float c_off[7][3] = {
    {0.f,0.f,0.f},{0.5f,0.f,0.f},{0.f,0.5f,0.f},{0.f,0.f,0.5f},
    {-0.5f,0.f,0.f},{0.f,-0.5f,0.f},{0.f,0.f,-0.5f}
};

__device__ __forceinline__ float softplusf(float x) {
    return fmaxf(x, 0.f) + log1pf(__expf(-fabsf(x)));
}
__device__ __forceinline__ float sigmoidf(float x) {
    return 1.f / (1.f + __expf(-x));
}

// Block-sum reduce; result valid on thread 0.
__device__ __forceinline__ float block_reduce(float v, float* sh) {
    __syncthreads();  // allow shared reuse across consecutive calls
    #pragma unroll
    for (int o = 16; o; o >>= 1) v += __shfl_down_sync(0xffffffffu, v, o);
    int lane = threadIdx.x & 31, w = threadIdx.x >> 5;
    if (lane == 0) sh[w] = v;
    __syncthreads();
    if (w == 0) {
        v = (lane < (int)(blockDim.x >> 5)) ? sh[lane] : 0.f;
        #pragma unroll
        for (int o = 16; o; o >>= 1) v += __shfl_down_sync(0xffffffffu, v, o);
    }
    return v;
}

// Candidate geometry: validity + cell index + box geometry.
__device__ __forceinline__ bool cand_geom(
    int tid, const float* __restrict__ targets, const float* __restrict__ anchor,
    int& cell, float& tbx, float& tby, float& tbz, float& rn, float& an,
    const float*& xrow)
{
    int t = tid & (NTAR - 1);
    int a = (tid >> 10) % AN;
    int o = tid / (AN * NTAR);
    const float* x = targets + t * FD;
    xrow = x;
    int b = t / TN;

    if (!(x[4] > 0.5f)) return false;                 // conf_m
    rn = x[3] * 0.25f;
    an = anchor[a] * 0.25f;
    float ratio = rn / an;
    if (!(fmaxf(ratio, 1.f / ratio) < 4.f)) return false;  // aok

    float gx = x[0] * 0.25f, gy = x[1] * 0.25f, gz = x[2] * 0.25f;

    bool fmv = true;
    if (o >= 1 && o <= 3) {
        float v = (o == 1) ? gx : (o == 2) ? gy : gz;
        fmv = ((v - floorf(v)) < 0.5f) && (v > 1.f);
    } else if (o >= 4) {
        float v0 = (o == 4) ? gx : (o == 5) ? gy : gz;
        float v = 64.f - v0;
        fmv = ((v - floorf(v)) < 0.5f) && (v > 1.f);
    }
    if (!fmv) return false;

    float fx = truncf(gx - c_off[o][0]);
    float fy = truncf(gy - c_off[o][1]);
    float fz = truncf(gz - c_off[o][2]);
    int gi = min(max(__float2int_rz(fx), 0), GR - 1);
    int gj = min(max(__float2int_rz(fy), 0), GR - 1);
    int gk = min(max(__float2int_rz(fz), 0), GR - 1);
    cell = (((b * AN + a) * GR + gk) * GR + gj) * GR + gi;
    tbx = gx - fx; tby = gy - fy; tbz = gz - fz;
    return true;
}

// Fused main kernel (R13 structure — best known: __ldcg sector-granular
// gather, 8 consecutive cells/thread, candidates piggybacked on blocks 0..83).
__global__ void __launch_bounds__(256) main_kernel(
    const float* __restrict__ p,
    const float* __restrict__ targets,
    const float* __restrict__ anchor)
{
    __shared__ float sh[32];
    int bid = blockIdx.x;

    // ---- obj part: 8 consecutive cells per thread, L2-only loads ----
    int i0 = (bid * 256 + threadIdx.x) * CELLS_PER_THREAD;
    float vobj[CELLS_PER_THREAD];
    #pragma unroll
    for (int k = 0; k < CELLS_PER_THREAD; k++)
        vobj[k] = __ldcg(p + (size_t)(i0 + k) * FD + 4);
    float s = 0.f;
    #pragma unroll
    for (int k = 0; k < CELLS_PER_THREAD; k++)
        s += softplusf(vobj[k]);

    // ---- candidate part (first CAND_BLOCKS blocks only) ----
    float lw = 0.f, lbb = 0.f, lcls = 0.f, lp4 = 0.f;
    bool is_cand_block = (bid < CAND_BLOCKS);
    if (is_cand_block) {
        int tid = bid * 256 + threadIdx.x;
        int cell; float tbx, tby, tbz, rn, an; const float* x;
        if (cand_geom(tid, targets, anchor, cell, tbx, tby, tbz, rn, an, x)) {
            const float* pr = p + (size_t)cell * FD;
            float pred[FD];
            #pragma unroll
            for (int i = 0; i < FD; i++) pred[i] = __ldg(pr + i);

            // pbox
            float c1x = sigmoidf(pred[0]) * 2.f - 0.5f;
            float c1y = sigmoidf(pred[1]) * 2.f - 0.5f;
            float c1z = sigmoidf(pred[2]) * 2.f - 0.5f;
            float s4  = sigmoidf(pred[3]) * 2.f;
            float r1  = s4 * s4 * an;

            // EIoU(pbox, tbox)
            const float eps = 1e-7f;
            float r2 = rn;
            float h1 = r1 * 0.5f, h2 = r2 * 0.5f;
            float lox = fmaxf(c1x - h1, tbx - h2), hix = fminf(c1x + h1, tbx + h2);
            float loy = fmaxf(c1y - h1, tby - h2), hiy = fminf(c1y + h1, tby + h2);
            float loz = fmaxf(c1z - h1, tbz - h2), hiz = fminf(c1z + h1, tbz + h2);
            float inter = fmaxf(hix - lox, 0.f) * fmaxf(hiy - loy, 0.f) * fmaxf(hiz - loz, 0.f);
            float uni = r1 * r1 * r1 + r2 * r2 * r2 - inter + eps;
            float iou = inter / uni;
            float cdx = fmaxf(c1x + h1, tbx + h2) - fminf(c1x - h1, tbx - h2);
            float cdy = fmaxf(c1y + h1, tby + h2) - fminf(c1y - h1, tby - h2);
            float cdz = fmaxf(c1z + h1, tbz + h2) - fminf(c1z - h1, tbz - h2);
            float dx = c1x - tbx, dy = c1y - tby, dz = c1z - tbz;
            float rho2 = dx * dx + dy * dy + dz * dz;
            float c2diag = cdx * cdx + cdy * cdy + cdz * cdz + eps;
            float dr = r1 - r2; float dr2 = dr * dr;
            float size_pen = dr2 / (cdx * cdx + eps) + dr2 / (cdy * cdy + eps) + dr2 / (cdz * cdz + eps);
            float ei = iou - rho2 / c2diag - size_pen;

            lw  = 1.f;
            lbb = 1.f - ei;

            // class BCE (tcls one-hot 0/1)
            float cs = 0.f;
            #pragma unroll
            for (int c = 0; c < CN; c++) {
                float l = pred[5 + c];
                float tc = x[5 + c];
                cs += tc * softplusf(-l) + (1.f - tc) * softplusf(l);
            }
            lcls = cs;

            // tobj dedup (generation scheme): first claimant this launch sees
            // a stored value != cur. Winner value depends only on the cell ->
            // deterministic regardless of claim order. No cleanup required.
            unsigned cur = __ldcg(&g_gen) + 1u;
            if (atomicExch(&g_flags[cell], cur) != cur) lp4 = pred[4];
        }
    }

    // ---- reductions ----
    float v;
    v = block_reduce(s, sh);
    if (threadIdx.x == 0) atomicAdd(&g_acc[4], (double)v);
    if (is_cand_block) {
        v = block_reduce(lw,   sh); if (threadIdx.x == 0 && v != 0.f) atomicAdd(&g_acc[0], (double)v);
        v = block_reduce(lbb,  sh); if (threadIdx.x == 0 && v != 0.f) atomicAdd(&g_acc[1], (double)v);
        v = block_reduce(lcls, sh); if (threadIdx.x == 0 && v != 0.f) atomicAdd(&g_acc[2], (double)v);
        v = block_reduce(lp4,  sh); if (threadIdx.x == 0 && v != 0.f) atomicAdd(&g_acc[3], (double)v);
    }
}

// Tiny finalize: write outputs, reset accumulators, advance the generation.
// No flag clearing (generation dedup), no list walk -> a few hundred cycles.
__global__ void fin_kernel(float* out, int out_size)
{
    if (threadIdx.x == 0) {
        double sw   = g_acc[0];
        double sbb  = g_acc[1];
        double scls = g_acc[2];
        double sp4  = g_acc[3];
        double ssp  = g_acc[4];
        double nv = fmax(sw, 1.0);
        double lb = sbb / nv;                       // loss_bbox * 1.0
        double lc = 10.0 * scls / (nv * (double)CN);
        double lo = 20.0 * (ssp - sp4) / (double)NCELL;
        if (out_size > 0) out[0] = (float)((lb + lo + lc) * (double)BS);
        if (out_size > 1) out[1] = (float)lo;
        if (out_size > 2) out[2] = (float)lc;
        #pragma unroll
        for (int i = 0; i < 5; i++) g_acc[i] = 0.0;
        g_gen = g_gen + 1u;
    }
}

extern "C" void kernel_launch(void* const* d_in, const int* in_sizes, int n_in,
                              void* d_out, int out_size)
{
    const float* p      = (const float*)d_in[0];
    const float* tg     = (const float*)d_in[1];
    const float* anchor = (const float*)d_in[2];
    float* out = (float*)d_out;

    main_kernel<<<MAIN_BLOCKS, 256>>>(p, tg, anchor);
    fin_kernel<<<1, 32>>>(out, out_size);
}

// round 15
// speedup vs baseline: 1.4641x; 1.0556x over previous
#include <cuda_runtime.h>
#include <math.h>

// Problem constants (fixed shapes from reference)
#define BS     4
#define AN     3
#define GR     64
#define CN     13
#define FD     18
#define TN     256
#define NTAR   (BS*TN)          // 1024
#define NCAND  (7*AN*NTAR)      // 21504
#define NCELL  (BS*AN*GR*GR*GR) // 3145728

#define CELLS_PER_THREAD 8
#define MAIN_BLOCKS (NCELL / (256 * CELLS_PER_THREAD))  // 1536
#define CAND_BLOCKS (NCAND / 256)                        // 84

// Device state.
// Accumulators: 0=sum_w, 1=sum_bbox, 2=sum_cls, 3=sum_p4_set, 4=sum_softplus
// (zero at load; the last-block epilogue re-zeroes each launch).
// Dedup uses a GENERATION scheme: launch k claims cells by writing gen=k+1
// into g_flags via atomicExch; first claimant sees old != k+1. g_gen is
// incremented once per launch by the epilogue, so no flag clearing is ever
// needed and every launch performs identical work -> identical output.
__device__ double   g_acc[5];
__device__ unsigned g_flags[NCELL];
__device__ unsigned g_gen;
__device__ unsigned g_done;

__constant__ float c_off[7][3] = {
    {0.f,0.f,0.f},{0.5f,0.f,0.f},{0.f,0.5f,0.f},{0.f,0.f,0.5f},
    {-0.5f,0.f,0.f},{0.f,-0.5f,0.f},{0.f,0.f,-0.5f}
};

__device__ __forceinline__ float softplusf(float x) {
    return fmaxf(x, 0.f) + log1pf(__expf(-fabsf(x)));
}
__device__ __forceinline__ float sigmoidf(float x) {
    return 1.f / (1.f + __expf(-x));
}

// Block-sum reduce; result valid on thread 0.
__device__ __forceinline__ float block_reduce(float v, float* sh) {
    __syncthreads();  // allow shared reuse across consecutive calls
    #pragma unroll
    for (int o = 16; o; o >>= 1) v += __shfl_down_sync(0xffffffffu, v, o);
    int lane = threadIdx.x & 31, w = threadIdx.x >> 5;
    if (lane == 0) sh[w] = v;
    __syncthreads();
    if (w == 0) {
        v = (lane < (int)(blockDim.x >> 5)) ? sh[lane] : 0.f;
        #pragma unroll
        for (int o = 16; o; o >>= 1) v += __shfl_down_sync(0xffffffffu, v, o);
    }
    return v;
}

// Candidate geometry: validity + cell index + box geometry.
__device__ __forceinline__ bool cand_geom(
    int tid, const float* __restrict__ targets, const float* __restrict__ anchor,
    int& cell, float& tbx, float& tby, float& tbz, float& rn, float& an,
    const float*& xrow)
{
    int t = tid & (NTAR - 1);
    int a = (tid >> 10) % AN;
    int o = tid / (AN * NTAR);
    const float* x = targets + t * FD;
    xrow = x;
    int b = t / TN;

    if (!(x[4] > 0.5f)) return false;                 // conf_m
    rn = x[3] * 0.25f;
    an = anchor[a] * 0.25f;
    float ratio = rn / an;
    if (!(fmaxf(ratio, 1.f / ratio) < 4.f)) return false;  // aok

    float gx = x[0] * 0.25f, gy = x[1] * 0.25f, gz = x[2] * 0.25f;

    bool fmv = true;
    if (o >= 1 && o <= 3) {
        float v = (o == 1) ? gx : (o == 2) ? gy : gz;
        fmv = ((v - floorf(v)) < 0.5f) && (v > 1.f);
    } else if (o >= 4) {
        float v0 = (o == 4) ? gx : (o == 5) ? gy : gz;
        float v = 64.f - v0;
        fmv = ((v - floorf(v)) < 0.5f) && (v > 1.f);
    }
    if (!fmv) return false;

    float fx = truncf(gx - c_off[o][0]);
    float fy = truncf(gy - c_off[o][1]);
    float fz = truncf(gz - c_off[o][2]);
    int gi = min(max(__float2int_rz(fx), 0), GR - 1);
    int gj = min(max(__float2int_rz(fy), 0), GR - 1);
    int gk = min(max(__float2int_rz(fz), 0), GR - 1);
    cell = (((b * AN + a) * GR + gk) * GR + gj) * GR + gi;
    tbx = gx - fx; tby = gy - fy; tbz = gz - fz;
    return true;
}

// Single fused kernel (R13/R14 best-known structure + last-block epilogue):
//  - all blocks: __ldcg sector-granular ch-4 gather, 8 consecutive cells/thread
//  - blocks 0..83: candidate EIoU/cls work, generation-based tobj dedup
//  - last finishing block: write outputs, reset accumulators, bump generation
__global__ void __launch_bounds__(256) main_kernel(
    const float* __restrict__ p,
    const float* __restrict__ targets,
    const float* __restrict__ anchor,
    float* __restrict__ out, int out_size)
{
    __shared__ float sh[32];
    __shared__ int s_last;
    int bid = blockIdx.x;

    // ---- obj part: 8 consecutive cells per thread, L2-only loads ----
    int i0 = (bid * 256 + threadIdx.x) * CELLS_PER_THREAD;
    float vobj[CELLS_PER_THREAD];
    #pragma unroll
    for (int k = 0; k < CELLS_PER_THREAD; k++)
        vobj[k] = __ldcg(p + (size_t)(i0 + k) * FD + 4);
    float s = 0.f;
    #pragma unroll
    for (int k = 0; k < CELLS_PER_THREAD; k++)
        s += softplusf(vobj[k]);

    // ---- candidate part (first CAND_BLOCKS blocks only) ----
    float lw = 0.f, lbb = 0.f, lcls = 0.f, lp4 = 0.f;
    bool is_cand_block = (bid < CAND_BLOCKS);
    if (is_cand_block) {
        int tid = bid * 256 + threadIdx.x;
        int cell; float tbx, tby, tbz, rn, an; const float* x;
        if (cand_geom(tid, targets, anchor, cell, tbx, tby, tbz, rn, an, x)) {
            const float* pr = p + (size_t)cell * FD;
            float pred[FD];
            #pragma unroll
            for (int i = 0; i < FD; i++) pred[i] = __ldg(pr + i);

            // pbox
            float c1x = sigmoidf(pred[0]) * 2.f - 0.5f;
            float c1y = sigmoidf(pred[1]) * 2.f - 0.5f;
            float c1z = sigmoidf(pred[2]) * 2.f - 0.5f;
            float s4  = sigmoidf(pred[3]) * 2.f;
            float r1  = s4 * s4 * an;

            // EIoU(pbox, tbox)
            const float eps = 1e-7f;
            float r2 = rn;
            float h1 = r1 * 0.5f, h2 = r2 * 0.5f;
            float lox = fmaxf(c1x - h1, tbx - h2), hix = fminf(c1x + h1, tbx + h2);
            float loy = fmaxf(c1y - h1, tby - h2), hiy = fminf(c1y + h1, tby + h2);
            float loz = fmaxf(c1z - h1, tbz - h2), hiz = fminf(c1z + h1, tbz + h2);
            float inter = fmaxf(hix - lox, 0.f) * fmaxf(hiy - loy, 0.f) * fmaxf(hiz - loz, 0.f);
            float uni = r1 * r1 * r1 + r2 * r2 * r2 - inter + eps;
            float iou = inter / uni;
            float cdx = fmaxf(c1x + h1, tbx + h2) - fminf(c1x - h1, tbx - h2);
            float cdy = fmaxf(c1y + h1, tby + h2) - fminf(c1y - h1, tby - h2);
            float cdz = fmaxf(c1z + h1, tbz + h2) - fminf(c1z - h1, tbz - h2);
            float dx = c1x - tbx, dy = c1y - tby, dz = c1z - tbz;
            float rho2 = dx * dx + dy * dy + dz * dz;
            float c2diag = cdx * cdx + cdy * cdy + cdz * cdz + eps;
            float dr = r1 - r2; float dr2 = dr * dr;
            float size_pen = dr2 / (cdx * cdx + eps) + dr2 / (cdy * cdy + eps) + dr2 / (cdz * cdz + eps);
            float ei = iou - rho2 / c2diag - size_pen;

            lw  = 1.f;
            lbb = 1.f - ei;

            // class BCE (tcls one-hot 0/1)
            float cs = 0.f;
            #pragma unroll
            for (int c = 0; c < CN; c++) {
                float l = pred[5 + c];
                float tc = x[5 + c];
                cs += tc * softplusf(-l) + (1.f - tc) * softplusf(l);
            }
            lcls = cs;

            // tobj dedup (generation scheme): first claimant this launch sees
            // a stored value != cur. Winner value depends only on the cell ->
            // deterministic regardless of claim order. No cleanup required.
            unsigned cur = __ldcg(&g_gen) + 1u;
            if (atomicExch(&g_flags[cell], cur) != cur) lp4 = pred[4];
        }
    }

    // ---- reductions ----
    float v;
    v = block_reduce(s, sh);
    if (threadIdx.x == 0) atomicAdd(&g_acc[4], (double)v);
    if (is_cand_block) {
        v = block_reduce(lw,   sh); if (threadIdx.x == 0 && v != 0.f) atomicAdd(&g_acc[0], (double)v);
        v = block_reduce(lbb,  sh); if (threadIdx.x == 0 && v != 0.f) atomicAdd(&g_acc[1], (double)v);
        v = block_reduce(lcls, sh); if (threadIdx.x == 0 && v != 0.f) atomicAdd(&g_acc[2], (double)v);
        v = block_reduce(lp4,  sh); if (threadIdx.x == 0 && v != 0.f) atomicAdd(&g_acc[3], (double)v);
    }

    // ---- last-block epilogue: finalize + advance generation ----
    if (threadIdx.x == 0) {
        __threadfence();
        unsigned t = atomicAdd(&g_done, 1u);
        s_last = (t == (unsigned)(gridDim.x - 1));
    }
    __syncthreads();
    if (s_last && threadIdx.x == 0) {
        volatile double* acc = g_acc;
        double sw   = acc[0];
        double sbb  = acc[1];
        double scls = acc[2];
        double sp4  = acc[3];
        double ssp  = acc[4];
        double nv = fmax(sw, 1.0);
        double lb = sbb / nv;                       // loss_bbox * 1.0
        double lc = 10.0 * scls / (nv * (double)CN);
        double lo = 20.0 * (ssp - sp4) / (double)NCELL;
        if (out_size > 0) out[0] = (float)((lb + lo + lc) * (double)BS);
        if (out_size > 1) out[1] = (float)lo;
        if (out_size > 2) out[2] = (float)lc;
        #pragma unroll
        for (int i = 0; i < 5; i++) g_acc[i] = 0.0;
        g_gen  = g_gen + 1u;
        g_done = 0u;
    }
}

extern "C" void kernel_launch(void* const* d_in, const int* in_sizes, int n_in,
                              void* d_out, int out_size)
{
    const float* p      = (const float*)d_in[0];
    const float* tg     = (const float*)d_in[1];
    const float* anchor = (const float*)d_in[2];
    float* out = (float*)d_out;

    main_kernel<<<MAIN_BLOCKS, 256>>>(p, tg, anchor, out, out_size);
}